// round 1
// baseline (speedup 1.0000x reference)
#include <cuda_runtime.h>

#define THREADS 256
#define BDIM 64
#define HDIM 8
#define MDIM 1024
#define CDIM 128
#define MIDD 64
#define TROWS 64
#define NTILES (MDIM / TROWS)
#define KS_STRIDE 66

// shared memory layout (float offsets)
#define OFF_QWD 0
#define SZ_QWD (CDIM * MIDD * 2)        /* 16384 : qw duplicated pairs */
#define OFF_KS (OFF_QWD + SZ_QWD)       /* 16384 */
#define SZ_KS (CDIM * KS_STRIDE)        /* 8448  : transposed key tile */
#define OFF_LG (OFF_KS + SZ_KS)         /* 24832 : logits/alphas */
#define OFF_MASK (OFF_LG + MDIM)        /* 25856 */
#define OFF_POOL (OFF_MASK + MDIM)      /* 26880 */
#define OFF_RED (OFF_POOL + MIDD)       /* 26944 */
#define SMEM_FLOATS (OFF_RED + 32)      /* 26976 */
#define SMEM_BYTES (SMEM_FLOATS * 4)    /* 107904 B */

typedef unsigned long long u64;

__device__ __forceinline__ u64 ffma2(u64 a, u64 b, u64 c) {
    u64 d;
    asm("fma.rn.f32x2 %0, %1, %2, %3;" : "=l"(d) : "l"(a), "l"(b), "l"(c));
    return d;
}
__device__ __forceinline__ float f2lo(u64 v) { return __uint_as_float((unsigned)v); }
__device__ __forceinline__ float f2hi(u64 v) { return __uint_as_float((unsigned)(v >> 32)); }

__global__ void __launch_bounds__(THREADS, 2) scatt_kernel(
    const float* __restrict__ q, const float* __restrict__ kf,
    const int* __restrict__ msk, const float* __restrict__ v1,
    const float* __restrict__ v2g, const float* __restrict__ wb,
    const float* __restrict__ bb, const float* __restrict__ wl,
    const float* __restrict__ bl, const float* __restrict__ wl2,
    const float* __restrict__ bl2, float* __restrict__ out)
{
    extern __shared__ float sm[];
    float* sqwd  = sm + OFF_QWD;
    float* sks   = sm + OFF_KS;
    float* slg   = sm + OFF_LG;
    float* smask = sm + OFF_MASK;
    float* spool = sm + OFF_POOL;
    float* sred  = sm + OFF_RED;

    const int tid = threadIdx.x;
    const int bh = blockIdx.x;
    const int b = bh >> 3;
    const int h = bh & 7;

    const float* qv  = q   + bh * CDIM;
    const float* kfp = kf  + (size_t)bh * MDIM * CDIM;
    const float* v2p = v2g + (size_t)bh * MDIM * CDIM;

    if (tid == 0) sred[0] = 0.f;
    __syncthreads();

    // qw duplicated: qwd[i][2o..2o+1] = q[i]*W_basic[h][i][o]
    for (int idx = tid; idx < CDIM * MIDD; idx += THREADS) {
        int i = idx >> 6, o = idx & 63;
        float v = qv[i] * wb[h * CDIM * MIDD + idx];
        ((float2*)sqwd)[i * MIDD + o] = make_float2(v, v);
    }
    // mask to smem + count (integer-valued -> order independent, exact)
    float cl = 0.f;
    for (int m = tid; m < MDIM; m += THREADS) {
        float mv = (float)msk[b * MDIM + m];
        smask[m] = mv;
        cl += mv;
    }
    #pragma unroll
    for (int off = 16; off; off >>= 1) cl += __shfl_xor_sync(0xffffffffu, cl, off);
    if ((tid & 31) == 0) atomicAdd(&sred[0], cl);
    __syncthreads();

    const int og = tid & 15;   // o-group: 4 columns og*4..og*4+3
    const int mq = tid >> 4;   // m-quad: rows mq*4..mq*4+3 within tile
    float bbv[4], wlv[4];
    #pragma unroll
    for (int c = 0; c < 4; ++c) {
        bbv[c] = bb[h * MIDD + og * 4 + c];
        wlv[c] = wl[h * MIDD + og * 4 + c];
    }
    const float blv = bl[h];
    float pacc[4] = {0.f, 0.f, 0.f, 0.f};

    for (int t = 0; t < NTILES; ++t) {
        const int m0 = t * TROWS;
        // cooperative transposed tile load: sks[i][m_local]
        for (int idx = tid; idx < TROWS * CDIM / 4; idx += THREADS) {
            int r = idx >> 5;
            int c4 = (idx & 31) << 2;
            float4 v = *(const float4*)(kfp + (size_t)(m0 + r) * CDIM + c4);
            sks[(c4 + 0) * KS_STRIDE + r] = v.x;
            sks[(c4 + 1) * KS_STRIDE + r] = v.y;
            sks[(c4 + 2) * KS_STRIDE + r] = v.z;
            sks[(c4 + 3) * KS_STRIDE + r] = v.w;
        }
        __syncthreads();

        u64 acc[2][4];
        #pragma unroll
        for (int rp = 0; rp < 2; ++rp)
            #pragma unroll
            for (int c = 0; c < 4; ++c) acc[rp][c] = 0ull;

        #pragma unroll 4
        for (int i = 0; i < CDIM; ++i) {
            const float* kp = sks + i * KS_STRIDE + mq * 4;
            u64 k01 = *(const u64*)kp;
            u64 k23 = *(const u64*)(kp + 2);
            const u64* wp = (const u64*)(sqwd + i * (MIDD * 2) + og * 8);
            #pragma unroll
            for (int c = 0; c < 4; ++c) {
                u64 w = wp[c];
                acc[0][c] = ffma2(k01, w, acc[0][c]);
                acc[1][c] = ffma2(k23, w, acc[1][c]);
            }
        }

        // epilogue: bias + relu + masked pool partials + logit projection
        #pragma unroll
        for (int rp = 0; rp < 2; ++rp) {
            #pragma unroll
            for (int sub = 0; sub < 2; ++sub) {
                int m = m0 + mq * 4 + rp * 2 + sub;
                float mk = smask[m];
                float ls = 0.f;
                #pragma unroll
                for (int c = 0; c < 4; ++c) {
                    float a = sub ? f2hi(acc[rp][c]) : f2lo(acc[rp][c]);
                    a += bbv[c];
                    a = fmaxf(a, 0.f);
                    pacc[c] = fmaf(a, mk, pacc[c]);
                    ls = fmaf(a, wlv[c], ls);
                }
                ls += __shfl_down_sync(0xffffffffu, ls, 8, 16);
                ls += __shfl_down_sync(0xffffffffu, ls, 4, 16);
                ls += __shfl_down_sync(0xffffffffu, ls, 2, 16);
                ls += __shfl_down_sync(0xffffffffu, ls, 1, 16);
                if (og == 0) slg[m] = (mk == 0.f) ? -1e9f : (ls + blv);
            }
        }
        __syncthreads();
    }

    // deterministic pool reduction: 16 mq-partials per o (reuse sks)
    #pragma unroll
    for (int c = 0; c < 4; ++c) sks[mq * 64 + og * 4 + c] = pacc[c];
    __syncthreads();
    if (tid < MIDD) {
        float s = 0.f;
        #pragma unroll
        for (int k = 0; k < 16; ++k) s += sks[k * 64 + tid];
        spool[tid] = s;
    }
    __syncthreads();

    // softmax over slg[0..1023]
    float lm = -3.0e38f;
    for (int m = tid; m < MDIM; m += THREADS) lm = fmaxf(lm, slg[m]);
    #pragma unroll
    for (int off = 16; off; off >>= 1) lm = fmaxf(lm, __shfl_xor_sync(0xffffffffu, lm, off));
    if ((tid & 31) == 0) sred[1 + (tid >> 5)] = lm;
    __syncthreads();
    if (tid == 0) {
        float g = sred[1];
        #pragma unroll
        for (int w = 1; w < 8; ++w) g = fmaxf(g, sred[1 + w]);
        sred[9] = g;
    }
    __syncthreads();
    const float gmax = sred[9];
    float es = 0.f;
    for (int m = tid; m < MDIM; m += THREADS) es += expf(slg[m] - gmax);
    #pragma unroll
    for (int off = 16; off; off >>= 1) es += __shfl_xor_sync(0xffffffffu, es, off);
    if ((tid & 31) == 0) sred[10 + (tid >> 5)] = es;
    __syncthreads();
    if (tid == 0) {
        float s = 0.f;
        #pragma unroll
        for (int w = 0; w < 8; ++w) s += sred[10 + w];
        sred[18] = 1.f / s;
    }
    __syncthreads();
    const float inv = sred[18];
    for (int m = tid; m < MDIM; m += THREADS) slg[m] = expf(slg[m] - gmax) * inv;
    __syncthreads();

    // v2 = sum_m alpha[m] * value2[m, :]  (8 m-segments x 32 float4 channels)
    {
        const int cb = (tid & 31) << 2;
        const int seg = tid >> 5;
        const float* vp = v2p + cb;
        float4 va = make_float4(0.f, 0.f, 0.f, 0.f);
        #pragma unroll 4
        for (int m = seg * 128; m < seg * 128 + 128; ++m) {
            float al = slg[m];
            float4 x = *(const float4*)(vp + (size_t)m * CDIM);
            va.x = fmaf(al, x.x, va.x);
            va.y = fmaf(al, x.y, va.y);
            va.z = fmaf(al, x.z, va.z);
            va.w = fmaf(al, x.w, va.w);
        }
        // deterministic: stage per-segment partials in sks (free now)
        sks[seg * 128 + cb + 0] = va.x;
        sks[seg * 128 + cb + 1] = va.y;
        sks[seg * 128 + cb + 2] = va.z;
        sks[seg * 128 + cb + 3] = va.w;
    }
    __syncthreads();

    // alpha_channel + final output
    if (tid < CDIM) {
        const int c = tid;
        float v2c = 0.f;
        #pragma unroll
        for (int k = 0; k < 8; ++k) v2c += sks[k * 128 + c];
        const float invc = 1.f / sred[0];
        float x = bl2[h * CDIM + c];
        const float* w2 = wl2 + h * MIDD * CDIM + c;
        #pragma unroll 8
        for (int o = 0; o < MIDD; ++o) x = fmaf(spool[o] * invc, w2[o * CDIM], x);
        float sig = 1.f / (1.f + expf(-x));
        out[bh * CDIM + c] = v1[bh * CDIM + c] * v2c * sig;
    }
}

extern "C" void kernel_launch(void* const* d_in, const int* in_sizes, int n_in,
                              void* d_out, int out_size) {
    const float* q   = (const float*)d_in[0];
    const float* kf  = (const float*)d_in[1];
    const int*   msk = (const int*)d_in[2];
    const float* v1  = (const float*)d_in[3];
    const float* v2  = (const float*)d_in[4];
    const float* wb  = (const float*)d_in[5];
    const float* bbp = (const float*)d_in[6];
    const float* wlp = (const float*)d_in[7];
    const float* blp = (const float*)d_in[8];
    const float* wl2 = (const float*)d_in[9];
    const float* bl2 = (const float*)d_in[10];
    float* out = (float*)d_out;

    cudaFuncSetAttribute(scatt_kernel, cudaFuncAttributeMaxDynamicSharedMemorySize, SMEM_BYTES);
    scatt_kernel<<<BDIM * HDIM, THREADS, SMEM_BYTES>>>(q, kf, msk, v1, v2, wb, bbp, wlp, blp, wl2, bl2, out);
}

// round 2
// speedup vs baseline: 3.5882x; 3.5882x over previous
#include <cuda_runtime.h>

#define THREADS 256
#define BDIM 64
#define HDIM 8
#define MDIM 1024
#define CDIM 128
#define MIDD 64
#define TROWS 128
#define NTILES (MDIM / TROWS)

// shared memory layout (float offsets)
#define OFF_K 0
#define SZ_K (TROWS * CDIM)            /* 16384 floats, 64KB, swizzled row-major key tile */
#define OFF_QW (OFF_K + SZ_K)          /* 16384 : qwT [o][ipair] u64 words, swizzled (8192 floats) */
#define SZ_QW (MIDD * 64 * 2)
#define OFF_LG (OFF_QW + SZ_QW)        /* 24576 : logits / alphas */
#define OFF_MASK (OFF_LG + MDIM)       /* 25600 */
#define OFF_POOL (OFF_MASK + MDIM)     /* 26624 */
#define OFF_RED (OFF_POOL + MIDD)      /* 26688 */
#define OFF_BW (OFF_RED + 32)          /* 26720 : bb (64) + wl (64) */
#define SMEM_FLOATS (OFF_BW + 128)     /* 26848 */
#define SMEM_BYTES (SMEM_FLOATS * 4)   /* 107392 B -> 2 CTAs/SM */

typedef unsigned long long u64;

__device__ __forceinline__ u64 ffma2(u64 a, u64 b, u64 c) {
    u64 d;
    asm("fma.rn.f32x2 %0, %1, %2, %3;" : "=l"(d) : "l"(a), "l"(b), "l"(c));
    return d;
}
__device__ __forceinline__ float f2lo(u64 v) { return __uint_as_float((unsigned)v); }
__device__ __forceinline__ float f2hi(u64 v) { return __uint_as_float((unsigned)(v >> 32)); }

__global__ void __launch_bounds__(THREADS, 2) scatt_kernel(
    const float* __restrict__ q, const float* __restrict__ kf,
    const int* __restrict__ msk, const float* __restrict__ v1,
    const float* __restrict__ v2g, const float* __restrict__ wb,
    const float* __restrict__ bb, const float* __restrict__ wl,
    const float* __restrict__ bl, const float* __restrict__ wl2,
    const float* __restrict__ bl2, float* __restrict__ out)
{
    extern __shared__ float sm[];
    float* slg   = sm + OFF_LG;
    float* smask = sm + OFF_MASK;
    float* spool = sm + OFF_POOL;
    float* sred  = sm + OFF_RED;
    float* sbw   = sm + OFF_BW;

    const int tid = threadIdx.x;
    const int bh = blockIdx.x;
    const int b = bh >> 3;
    const int h = bh & 7;

    const float* qv  = q   + bh * CDIM;
    const float* kfp = kf  + (size_t)bh * MDIM * CDIM;
    const float* v2p = v2g + (size_t)bh * MDIM * CDIM;
    const float* wbh = wb  + h * CDIM * MIDD;

    if (tid == 0) sred[0] = 0.f;
    __syncthreads();

    // Build qwT: word (o, ip) = (q[2ip]*W[2ip][o], q[2ip+1]*W[2ip+1][o])
    // stored at u64 index o*64 + (ip ^ (o & 15)). Coalesced over o.
    {
        float2* wq2 = (float2*)(sm + OFF_QW);
        for (int widx = tid; widx < MIDD * 64; widx += THREADS) {
            int o = widx & 63;
            int ip = widx >> 6;
            int i = ip << 1;
            float a0 = qv[i]     * wbh[i * MIDD + o];
            float a1 = qv[i + 1] * wbh[(i + 1) * MIDD + o];
            wq2[o * 64 + (ip ^ (o & 15))] = make_float2(a0, a1);
        }
    }
    // mask + exact count
    float cl = 0.f;
    for (int m = tid; m < MDIM; m += THREADS) {
        float mv = (float)msk[b * MDIM + m];
        smask[m] = mv;
        cl += mv;
    }
    #pragma unroll
    for (int off = 16; off; off >>= 1) cl += __shfl_xor_sync(0xffffffffu, cl, off);
    if ((tid & 31) == 0) atomicAdd(&sred[0], cl);
    if (tid < MIDD) { sbw[tid] = bb[h * MIDD + tid]; sbw[MIDD + tid] = wl[h * MIDD + tid]; }

    const int og = tid & 7;    // 8 o-groups; thread's o-cols: c*8+og, c=0..7
    const int mg = tid >> 3;   // 32 m-groups x 4 rows = 128 rows/tile
    const float blv = bl[h];

    u64 acc[4][8];
    #pragma unroll
    for (int r = 0; r < 4; ++r)
        #pragma unroll
        for (int c = 0; c < 8; ++c) acc[r][c] = 0ull;
    float pacc[8] = {0.f,0.f,0.f,0.f,0.f,0.f,0.f,0.f};

    const u64* skw = (const u64*)sm;
    const u64* wqo = ((const u64*)(sm + OFF_QW)) + og * 64;
    const int rb0 = (mg * 4 + 0) * 64;
    const int rb1 = (mg * 4 + 1) * 64;
    const int rb2 = (mg * 4 + 2) * 64;
    const int rb3 = (mg * 4 + 3) * 64;
    const int swz = (mg & 3) << 2;

    for (int t = 0; t < NTILES; ++t) {
        const int m0 = t * TROWS;
        __syncthreads();
        // coalesced row-major fill with u64-granular XOR swizzle
        for (int idx = tid; idx < TROWS * (CDIM / 4); idx += THREADS) {
            int r = idx >> 5;
            int c4 = (idx & 31) << 2;
            float4 v = *(const float4*)(kfp + (size_t)(m0 + r) * CDIM + c4);
            int pw = (((c4 >> 1) ^ (r & 12)) >> 1);
            ((float4*)sm)[r * 32 + pw] = v;
        }
        __syncthreads();

        #pragma unroll 4
        for (int ip = 0; ip < 64; ++ip) {
            const int kx = ip ^ swz;
            u64 k0 = skw[rb0 + kx];
            u64 k1 = skw[rb1 + kx];
            u64 k2 = skw[rb2 + kx];
            u64 k3 = skw[rb3 + kx];
            const int wx0 = ip ^ og;
            const int wx1 = wx0 ^ 8;
            #pragma unroll
            for (int c = 0; c < 8; ++c) {
                u64 w = wqo[c * 512 + ((c & 1) ? wx1 : wx0)];
                acc[0][c] = ffma2(k0, w, acc[0][c]);
                acc[1][c] = ffma2(k1, w, acc[1][c]);
                acc[2][c] = ffma2(k2, w, acc[2][c]);
                acc[3][c] = ffma2(k3, w, acc[3][c]);
            }
        }

        // epilogue: bias + relu + pool partials + logit projection
        #pragma unroll
        for (int r = 0; r < 4; ++r) {
            int m = m0 + mg * 4 + r;
            float mk = smask[m];
            float ls = 0.f;
            #pragma unroll
            for (int c = 0; c < 8; ++c) {
                int o = c * 8 + og;
                float a = f2lo(acc[r][c]) + f2hi(acc[r][c]) + sbw[o];
                a = fmaxf(a, 0.f);
                pacc[c] = fmaf(a, mk, pacc[c]);
                ls = fmaf(a, sbw[MIDD + o], ls);
                acc[r][c] = 0ull;
            }
            ls += __shfl_down_sync(0xffffffffu, ls, 4, 8);
            ls += __shfl_down_sync(0xffffffffu, ls, 2, 8);
            ls += __shfl_down_sync(0xffffffffu, ls, 1, 8);
            if (og == 0) slg[m] = (mk == 0.f) ? -1e9f : (ls + blv);
        }
    }

    // pool reduction over mg: stage [32][64] in sk region
    __syncthreads();
    #pragma unroll
    for (int c = 0; c < 8; ++c) sm[mg * 64 + c * 8 + og] = pacc[c];
    __syncthreads();
    if (tid < MIDD) {
        float s = 0.f;
        #pragma unroll
        for (int k = 0; k < 32; ++k) s += sm[k * 64 + tid];
        spool[tid] = s;
    }
    __syncthreads();

    // softmax over slg
    float lm = -3.0e38f;
    for (int m = tid; m < MDIM; m += THREADS) lm = fmaxf(lm, slg[m]);
    #pragma unroll
    for (int off = 16; off; off >>= 1) lm = fmaxf(lm, __shfl_xor_sync(0xffffffffu, lm, off));
    if ((tid & 31) == 0) sred[1 + (tid >> 5)] = lm;
    __syncthreads();
    if (tid == 0) {
        float g = sred[1];
        #pragma unroll
        for (int w = 1; w < 8; ++w) g = fmaxf(g, sred[1 + w]);
        sred[9] = g;
    }
    __syncthreads();
    const float gmax = sred[9];
    float es = 0.f;
    for (int m = tid; m < MDIM; m += THREADS) es += expf(slg[m] - gmax);
    #pragma unroll
    for (int off = 16; off; off >>= 1) es += __shfl_xor_sync(0xffffffffu, es, off);
    if ((tid & 31) == 0) sred[10 + (tid >> 5)] = es;
    __syncthreads();
    if (tid == 0) {
        float s = 0.f;
        #pragma unroll
        for (int w = 0; w < 8; ++w) s += sred[10 + w];
        sred[18] = 1.f / s;
    }
    __syncthreads();
    const float inv = sred[18];
    for (int m = tid; m < MDIM; m += THREADS) slg[m] = expf(slg[m] - gmax) * inv;
    __syncthreads();

    // v2 = sum_m alpha[m] * value2[m, :]  (8 m-segments x 32 float4 channels)
    {
        const int cb = (tid & 31) << 2;
        const int seg = tid >> 5;
        const float* vp = v2p + cb;
        float4 va = make_float4(0.f, 0.f, 0.f, 0.f);
        #pragma unroll 4
        for (int m = seg * 128; m < seg * 128 + 128; ++m) {
            float al = slg[m];
            float4 x = *(const float4*)(vp + (size_t)m * CDIM);
            va.x = fmaf(al, x.x, va.x);
            va.y = fmaf(al, x.y, va.y);
            va.z = fmaf(al, x.z, va.z);
            va.w = fmaf(al, x.w, va.w);
        }
        sm[seg * 128 + cb + 0] = va.x;
        sm[seg * 128 + cb + 1] = va.y;
        sm[seg * 128 + cb + 2] = va.z;
        sm[seg * 128 + cb + 3] = va.w;
    }
    __syncthreads();

    // alpha_channel + final output
    if (tid < CDIM) {
        const int c = tid;
        float v2c = 0.f;
        #pragma unroll
        for (int k = 0; k < 8; ++k) v2c += sm[k * 128 + c];
        const float invc = 1.f / sred[0];
        float x = bl2[h * CDIM + c];
        const float* w2 = wl2 + h * MIDD * CDIM + c;
        #pragma unroll 8
        for (int o = 0; o < MIDD; ++o) x = fmaf(spool[o] * invc, w2[o * CDIM], x);
        float sig = 1.f / (1.f + expf(-x));
        out[bh * CDIM + c] = v1[bh * CDIM + c] * v2c * sig;
    }
}

extern "C" void kernel_launch(void* const* d_in, const int* in_sizes, int n_in,
                              void* d_out, int out_size) {
    const float* q   = (const float*)d_in[0];
    const float* kf  = (const float*)d_in[1];
    const int*   msk = (const int*)d_in[2];
    const float* v1  = (const float*)d_in[3];
    const float* v2  = (const float*)d_in[4];
    const float* wb  = (const float*)d_in[5];
    const float* bbp = (const float*)d_in[6];
    const float* wlp = (const float*)d_in[7];
    const float* blp = (const float*)d_in[8];
    const float* wl2 = (const float*)d_in[9];
    const float* bl2 = (const float*)d_in[10];
    float* out = (float*)d_out;

    cudaFuncSetAttribute(scatt_kernel, cudaFuncAttributeMaxDynamicSharedMemorySize, SMEM_BYTES);
    scatt_kernel<<<BDIM * HDIM, THREADS, SMEM_BYTES>>>(q, kf, msk, v1, v2, wb, bbp, wlp, blp, wl2, bl2, out);
}